// round 15
// baseline (speedup 1.0000x reference)
#include <cuda_runtime.h>
#include <cstddef>
#include <cstdint>

// Problem shape
#define BATCH 4096
#define FN    1024
#define RC    19
#define RD    1024
#define FLAT  (FN * RC)            // 19456 floats per conv batch row

#define CW_SMEM_BYTES (5 * RD * 4) // 20 KB: up to 5 staged R rows

// TMA score pipeline
#define STG_FLOATS 608             // 19*32 floats -> residue-clean stage
#define STG_BYTES  2432            // multiple of 16 (TMA requirement)
#define NSTAGES    32              // 19456 / 608 stages per batch

__device__ float g_W[FLAT];        // W[f][r] flat, matches conv's [f*19+r]

// ---------------------------------------------------------------------------
// Kernel 1: W = U @ R^T, 4-way split along r (unchanged from r14 keeper).
// ---------------------------------------------------------------------------
__global__ void compute_w_kernel(const float* __restrict__ U,
                                 const float* __restrict__ R) {
    extern __shared__ float sR[];
    const int tid  = threadIdx.x;
    const int lane = tid & 31;
    const int wid  = tid >> 5;

    const int q    = blockIdx.x & 3;
    const int fgrp = blockIdx.x >> 2;
    const int r0   = q * 5;
    const int nr   = (q < 3) ? 5 : 4;

    {
        float4* s4 = reinterpret_cast<float4*>(sR);
        const float4* g4 = reinterpret_cast<const float4*>(R + (size_t)r0 * RD);
        for (int k = tid; k < nr * 256; k += 256)
            s4[k] = g4[k];
    }
    __syncthreads();

    const int f = fgrp * 8 + wid;
    const float4* u4 = reinterpret_cast<const float4*>(U + (size_t)f * RD);
    float4 u[8];
#pragma unroll
    for (int i = 0; i < 8; i++) u[i] = u4[lane + 32 * i];

    for (int rr = 0; rr < nr; rr++) {
        const float4* r4 = reinterpret_cast<const float4*>(sR + (size_t)rr * RD);
        float s = 0.f;
#pragma unroll
        for (int i = 0; i < 8; i++) {
            float4 rv = r4[lane + 32 * i];
            s += u[i].x * rv.x + u[i].y * rv.y + u[i].z * rv.z + u[i].w * rv.w;
        }
#pragma unroll
        for (int off = 16; off > 0; off >>= 1)
            s += __shfl_xor_sync(0xffffffffu, s, off);
        if (lane == 0) g_W[f * RC + (r0 + rr)] = s;
    }
}

// ---------------------------------------------------------------------------
// Kernel 2: score[b][r] = sum_f conv[b][f][r] * W[f][r]  — TMA bulk pipeline.
//
// Warp-per-batch (b = blk*8 + wid), per-warp private 2-stage ring of 2432 B
// stages fed by cp.async.bulk (global->shared, mbarrier complete_tx).
// Elect lane issues expect_tx + bulk copy; all lanes try_wait.parity, then
// consume 19 scalar floats each (idx = q*32+lane, q=0..18) against
// L1-resident W. Stage base === 0 (mod 19), 32 mod 19 = 13:
//   r = (13q + lane) mod 19, slot k = 13q mod 19 (compile-time).
// Butterfly rotation for lane-residue base 1: peer slot (k - d) mod 19.
// ---------------------------------------------------------------------------
__global__ __launch_bounds__(256, 4)
void score_kernel(const float* __restrict__ conv, float* __restrict__ out) {
    __shared__ __align__(16) float    s_ring[8][2][STG_FLOATS]; // 38912 B
    __shared__ __align__(8)  uint64_t s_mbar[8][2];

    const int lane = threadIdx.x & 31;
    const int wid  = threadIdx.x >> 5;
    const int b    = blockIdx.x * 8 + wid;   // warp-per-batch

    const char* gsrc =
        reinterpret_cast<const char*>(conv + (size_t)b * FLAT);

    const uint32_t ring0 = (uint32_t)__cvta_generic_to_shared(&s_ring[wid][0][0]);
    const uint32_t ring1 = (uint32_t)__cvta_generic_to_shared(&s_ring[wid][1][0]);
    const uint32_t mbar0 = (uint32_t)__cvta_generic_to_shared(&s_mbar[wid][0]);
    const uint32_t mbar1 = (uint32_t)__cvta_generic_to_shared(&s_mbar[wid][1]);

    if (lane == 0) {
        asm volatile("mbarrier.init.shared.b64 [%0], 1;" :: "r"(mbar0) : "memory");
        asm volatile("mbarrier.init.shared.b64 [%0], 1;" :: "r"(mbar1) : "memory");
    }
    __syncwarp();
    asm volatile("fence.proxy.async.shared::cta;" ::: "memory");

    // Prologue: stages 0 and 1 in flight.
    if (lane == 0) {
        asm volatile("mbarrier.arrive.expect_tx.shared.b64 _, [%0], %1;"
                     :: "r"(mbar0), "r"(STG_BYTES) : "memory");
        asm volatile("cp.async.bulk.shared::cluster.global.mbarrier::complete_tx::bytes "
                     "[%0], [%1], %2, [%3];"
                     :: "r"(ring0), "l"(gsrc), "r"(STG_BYTES), "r"(mbar0) : "memory");
        asm volatile("mbarrier.arrive.expect_tx.shared.b64 _, [%0], %1;"
                     :: "r"(mbar1), "r"(STG_BYTES) : "memory");
        asm volatile("cp.async.bulk.shared::cluster.global.mbarrier::complete_tx::bytes "
                     "[%0], [%1], %2, [%3];"
                     :: "r"(ring1), "l"(gsrc + STG_BYTES), "r"(STG_BYTES), "r"(mbar1) : "memory");
    }

    float acc[RC];
#pragma unroll
    for (int k = 0; k < RC; k++) acc[k] = 0.f;

#pragma unroll
    for (int i = 0; i < NSTAGES; i++) {
        const int      slot   = i & 1;
        const uint32_t mbar   = slot ? mbar1 : mbar0;
        const uint32_t parity = (i >> 1) & 1;

        // All lanes wait for this stage's data (acquire).
        {
            uint32_t done;
            asm volatile(
                "{\n\t .reg .pred p;\n\t"
                "mbarrier.try_wait.parity.acquire.cta.shared::cta.b64 p, [%1], %2;\n\t"
                "selp.b32 %0, 1, 0, p;\n\t}"
                : "=r"(done) : "r"(mbar), "r"(parity) : "memory");
            if (!done) {
                asm volatile(
                    "{\n\t .reg .pred P1;\n\t"
                    "W_%=:\n\t"
                    "mbarrier.try_wait.parity.acquire.cta.shared::cta.b64 P1, [%0], %1, 0x989680;\n\t"
                    "@P1 bra.uni D_%=;\n\t"
                    "bra.uni W_%=;\n\t"
                    "D_%=:\n\t}"
                    :: "r"(mbar), "r"(parity) : "memory");
            }
        }

        // Consume: 19 scalar floats per lane, slots compile-time.
        const float* sp = &s_ring[wid][slot][0];
#pragma unroll
        for (int q = 0; q < RC; q++) {
            float cv = sp[q * 32 + lane];
            float wv = __ldg(&g_W[i * STG_FLOATS + q * 32 + lane]);
            acc[(13 * q) % RC] += cv * wv;
        }

        // Refill this slot with stage i+2.
        if (i + 2 < NSTAGES) {
            if (lane == 0) {
                const uint32_t rdst = slot ? ring1 : ring0;
                asm volatile("mbarrier.arrive.expect_tx.shared.b64 _, [%0], %1;"
                             :: "r"(mbar), "r"(STG_BYTES) : "memory");
                asm volatile("cp.async.bulk.shared::cluster.global.mbarrier::complete_tx::bytes "
                             "[%0], [%1], %2, [%3];"
                             :: "r"(rdst), "l"(gsrc + (size_t)(i + 2) * STG_BYTES),
                                "r"(STG_BYTES), "r"(mbar) : "memory");
            }
        }
    }

    // Butterfly: lane l slot k holds r=(l+k)%19; peer l+d has it at (k-d)%19.
#pragma unroll
    for (int d = 16; d >= 1; d >>= 1) {
        float tmp[RC];
#pragma unroll
        for (int k = 0; k < RC; k++) {
            const int s = (k + RC - d) % RC;
            tmp[k] = __shfl_down_sync(0xffffffffu, acc[s], d);
        }
#pragma unroll
        for (int k = 0; k < RC; k++) acc[k] += tmp[k];
    }

    // Lane 0: slot k == relation k. Direct stores, no atomics.
    if (lane == 0) {
        float* ob = out + (size_t)b * RC;
#pragma unroll
        for (int k = 0; k < RC; k++) ob[k] = acc[k];
    }
}

// ---------------------------------------------------------------------------
// Launch: two kernels, same stream. Graph-capturable, no allocations.
// ---------------------------------------------------------------------------
extern "C" void kernel_launch(void* const* d_in, const int* in_sizes, int n_in,
                              void* d_out, int out_size) {
    const float* conv = nullptr;
    const float* R    = nullptr;
    const float* U    = nullptr;
    for (int i = 0; i < n_in; i++) {
        long long n = in_sizes[i];
        if (n == (long long)BATCH * FN * RC)      conv = (const float*)d_in[i];
        else if (n == (long long)RC * RD)         R    = (const float*)d_in[i];
        else if (n == (long long)FN * RD)         U    = (const float*)d_in[i];
    }
    float* out = (float*)d_out;

    compute_w_kernel<<<512, 256, CW_SMEM_BYTES>>>(U, R);
    score_kernel<<<512, 256>>>(conv, out);
}